// round 1
// baseline (speedup 1.0000x reference)
#include <cuda_runtime.h>
#include <cstdint>
#include <cstddef>

#define SEQT 2048
#define NTAG 12
#define STARTT 10
#define STOPT 11
#define NEGV -10000.0f

// ---------------- scratch (device globals; no allocation) ----------------
__device__ float g_pre[2][SEQT][1024];      // 16 MB: input projections (i,f,g,o rows)
__device__ float g_hs[SEQT][512];           // 4 MB: [hf | hb] per timestep
__device__ float g_feats[SEQT][NTAG];
__device__ float g_P[SEQT / 32][NTAG][NTAG];

// ---------------- helpers ----------------
__device__ __forceinline__ unsigned long long fma2(unsigned long long a, unsigned long long b,
                                                   unsigned long long c) {
    unsigned long long d;
    asm("fma.rn.f32x2 %0, %1, %2, %3;" : "=l"(d) : "l"(a), "l"(b), "l"(c));
    return d;
}
__device__ __forceinline__ unsigned long long add2(unsigned long long a, unsigned long long b) {
    unsigned long long d;
    asm("add.rn.f32x2 %0, %1, %2;" : "=l"(d) : "l"(a), "l"(b));
    return d;
}
__device__ __forceinline__ float2 unpack2(unsigned long long u) {
    float2 f;
    asm("mov.b64 {%0, %1}, %2;" : "=f"(f.x), "=f"(f.y) : "l"(u));
    return f;
}
__device__ __forceinline__ unsigned smem_u32(const void* p) {
    return (unsigned)__cvta_generic_to_shared(p);
}
__device__ __forceinline__ unsigned ctarank() {
    unsigned r;
    asm("mov.u32 %0, %%cluster_ctarank;" : "=r"(r));
    return r;
}
__device__ __forceinline__ float sigf(float x) { return 1.f / (1.f + __expf(-x)); }
__device__ __forceinline__ float tanh_fast(float x) { return 2.f / (1.f + __expf(-2.f * x)) - 1.f; }

#define CLUSTER_SYNC_()                                                \
    do {                                                               \
        asm volatile("barrier.cluster.arrive.aligned;" ::: "memory");  \
        asm volatile("barrier.cluster.wait.aligned;" ::: "memory");    \
    } while (0)

// ---------------- kernel A: embedding gather + input projection ----------------
// pre[dir][t][row] = sum_e embed[sent[t]][e] * Wih[row][e] + bih[row] + bhh[row]
// grid 512 (256 per dir, 8 timesteps each), 256 threads, 4 rows/thread.
__global__ void __launch_bounds__(256) proj_kernel(
    const int* __restrict__ sent, const float* __restrict__ embed,
    const float* __restrict__ Wf, const float* __restrict__ bihf, const float* __restrict__ bhhf,
    const float* __restrict__ Wb, const float* __restrict__ bihb, const float* __restrict__ bhhb) {
    __shared__ __align__(16) float xs[8][256];
    int bx = blockIdx.x;
    int dir = bx >> 8;
    int t0 = (bx & 255) * 8;
    int tid = threadIdx.x;
#pragma unroll
    for (int i = 0; i < 8; i++) {
        xs[i][tid] = embed[(size_t)sent[t0 + i] * 256 + tid];
    }
    __syncthreads();
    const float* W = dir ? Wb : Wf;
    const float* bi = dir ? bihb : bihf;
    const float* bh = dir ? bhhb : bhhf;
    int r0 = tid * 4;
    float acc[8][4];
#pragma unroll
    for (int t = 0; t < 8; t++)
#pragma unroll
        for (int r = 0; r < 4; r++) acc[t][r] = 0.f;

#pragma unroll 1
    for (int e = 0; e < 256; e += 4) {
        float4 w0 = *(const float4*)(W + (size_t)(r0 + 0) * 256 + e);
        float4 w1 = *(const float4*)(W + (size_t)(r0 + 1) * 256 + e);
        float4 w2 = *(const float4*)(W + (size_t)(r0 + 2) * 256 + e);
        float4 w3 = *(const float4*)(W + (size_t)(r0 + 3) * 256 + e);
#pragma unroll
        for (int t = 0; t < 8; t++) {
            float4 xv = *(const float4*)(&xs[t][e]);
            acc[t][0] = fmaf(xv.x, w0.x, acc[t][0]);
            acc[t][0] = fmaf(xv.y, w0.y, acc[t][0]);
            acc[t][0] = fmaf(xv.z, w0.z, acc[t][0]);
            acc[t][0] = fmaf(xv.w, w0.w, acc[t][0]);
            acc[t][1] = fmaf(xv.x, w1.x, acc[t][1]);
            acc[t][1] = fmaf(xv.y, w1.y, acc[t][1]);
            acc[t][1] = fmaf(xv.z, w1.z, acc[t][1]);
            acc[t][1] = fmaf(xv.w, w1.w, acc[t][1]);
            acc[t][2] = fmaf(xv.x, w2.x, acc[t][2]);
            acc[t][2] = fmaf(xv.y, w2.y, acc[t][2]);
            acc[t][2] = fmaf(xv.z, w2.z, acc[t][2]);
            acc[t][2] = fmaf(xv.w, w2.w, acc[t][2]);
            acc[t][3] = fmaf(xv.x, w3.x, acc[t][3]);
            acc[t][3] = fmaf(xv.y, w3.y, acc[t][3]);
            acc[t][3] = fmaf(xv.z, w3.z, acc[t][3]);
            acc[t][3] = fmaf(xv.w, w3.w, acc[t][3]);
        }
    }
    float bs[4];
#pragma unroll
    for (int r = 0; r < 4; r++) bs[r] = bi[r0 + r] + bh[r0 + r];
#pragma unroll
    for (int t = 0; t < 8; t++) {
        float4 o;
        o.x = acc[t][0] + bs[0];
        o.y = acc[t][1] + bs[1];
        o.z = acc[t][2] + bs[2];
        o.w = acc[t][3] + bs[3];
        *(float4*)(&g_pre[dir][t0 + t][r0]) = o;
    }
}

// ---------------- kernel B: LSTM recurrence ----------------
// grid = 16 CTAs, cluster 8. CTAs 0-7: forward dir; 8-15: backward dir.
// Each CTA owns 32 hidden units j in [rank*32, rank*32+32): 128 gate rows.
// Thread t: l = t&127 (gate*32 + jl), seg = t>>7 (64-wide K segment).
// Weights in registers as f32x2 pairs; h exchanged via st.shared::cluster,
// double-buffered, one cluster barrier per step.
__global__ void __cluster_dims__(8, 1, 1) __launch_bounds__(512, 1)
lstm_kernel(const float* __restrict__ Whh_f, const float* __restrict__ Whh_b,
            const float* __restrict__ h0, const float* __restrict__ c0) {
    __shared__ __align__(16) float hbuf[2][256];
    __shared__ float part[512];
    __shared__ float gv[128];

    int tid = threadIdx.x;
    int dir = blockIdx.x >> 3;
    unsigned rank = ctarank();  // 0..7
    int l = tid & 127;
    int seg = tid >> 7;
    int gate = l >> 5;
    int jl = l & 31;
    int grow = gate * 256 + (int)rank * 32 + jl;  // global gate row 0..1023

    const float* Whh = dir ? Whh_b : Whh_f;
    // load this thread's 64 weights as 32 packed f32x2
    unsigned long long w2[32];
    {
        const ulonglong2* wp = (const ulonglong2*)(Whh + (size_t)grow * 256 + seg * 64);
#pragma unroll
        for (int i = 0; i < 16; i++) {
            ulonglong2 v = wp[i];
            w2[2 * i] = v.x;
            w2[2 * i + 1] = v.y;
        }
    }

    if (tid < 256) hbuf[0][tid] = h0[dir * 256 + tid];
    float c = 0.f;
    if (tid < 32) c = c0[dir * 256 + (int)rank * 32 + tid];
    const float* pre = &g_pre[dir][0][0];

    __syncthreads();
    CLUSTER_SYNC_();

#pragma unroll 1
    for (int s = 0; s < SEQT; s++) {
        int t = dir ? (SEQT - 1 - s) : s;
        float pv = 0.f;
        if (tid < 128) pv = pre[(size_t)t * 1024 + grow];  // hidden under compute

        int par = s & 1;
        const ulonglong2* hp = (const ulonglong2*)(&hbuf[par][seg * 64]);
        unsigned long long a0 = 0ull, a1 = 0ull, a2 = 0ull, a3 = 0ull;
#pragma unroll
        for (int i = 0; i < 16; i += 2) {
            ulonglong2 v0 = hp[i];
            ulonglong2 v1 = hp[i + 1];
            a0 = fma2(w2[2 * i + 0], v0.x, a0);
            a1 = fma2(w2[2 * i + 1], v0.y, a1);
            a2 = fma2(w2[2 * i + 2], v1.x, a2);
            a3 = fma2(w2[2 * i + 3], v1.y, a3);
        }
        a0 = add2(a0, a1);
        a2 = add2(a2, a3);
        a0 = add2(a0, a2);
        float2 fa = unpack2(a0);
        part[tid] = fa.x + fa.y;
        __syncthreads();

        if (tid < 128) {
            float g = part[tid] + part[tid + 128] + part[tid + 256] + part[tid + 384] + pv;
            gv[tid] = g;
        }
        __syncthreads();

        if (tid < 32) {
            float gi = sigf(gv[tid]);
            float gf = sigf(gv[32 + tid]);
            float gg = tanh_fast(gv[64 + tid]);
            float go = sigf(gv[96 + tid]);
            c = gf * c + gi * gg;
            float h = go * tanh_fast(c);
            g_hs[t][dir * 256 + (int)rank * 32 + tid] = h;
            unsigned la = smem_u32(&hbuf[par ^ 1][(int)rank * 32 + tid]);
#pragma unroll
            for (int r = 0; r < 8; r++) {
                asm volatile(
                    "{\n\t.reg .b32 ra;\n\t"
                    "mapa.shared::cluster.u32 ra, %0, %1;\n\t"
                    "st.shared::cluster.f32 [ra], %2;\n\t}"
                    :: "r"(la), "r"(r), "f"(h)
                    : "memory");
            }
        }
        CLUSTER_SYNC_();
    }
}

// ---------------- kernel C: emissions ----------------
// feats[t][n] = sum_k hs[t][k] * W_out[n][k] + b_out[n]
__global__ void __launch_bounds__(128) feats_kernel(const float* __restrict__ W_out,
                                                    const float* __restrict__ b_out) {
    int t = blockIdx.x;
    __shared__ __align__(16) float hs_s[512];
    int tid = threadIdx.x;
    ((float4*)hs_s)[tid] = ((const float4*)&g_hs[t][0])[tid];
    __syncthreads();
    int w = tid >> 5, lane = tid & 31;
    for (int tag = w; tag < NTAG; tag += 4) {
        float a = 0.f;
#pragma unroll
        for (int i = 0; i < 16; i++) {
            int k = lane + 32 * i;
            a = fmaf(hs_s[k], W_out[tag * 512 + k], a);
        }
#pragma unroll
        for (int off = 16; off > 0; off >>= 1) a += __shfl_xor_sync(0xffffffffu, a, off);
        if (lane == 0) g_feats[t][tag] = a + b_out[tag];
    }
}

// ---------------- kernel D: CRF chunked log-semiring products ----------------
// P_c = M_{t0+31} (x) ... (x) M_{t0}, M_t[n,p] = T[n,p] + emit_t[n]
__global__ void __launch_bounds__(144) crf_chunk_kernel(const float* __restrict__ trans) {
    __shared__ float T[NTAG][NTAG];
    __shared__ float P[2][NTAG][NTAG + 1];
    __shared__ float em[32][NTAG];
    int tid = threadIdx.x;
    int n = tid / NTAG, p = tid - n * NTAG;
    int t0 = blockIdx.x * 32;
    T[n][p] = trans[tid];
    for (int idx = tid; idx < 32 * NTAG; idx += 144)
        em[idx / NTAG][idx % NTAG] = g_feats[t0 + idx / NTAG][idx % NTAG];
    __syncthreads();
    P[0][n][p] = T[n][p] + em[0][n];
    __syncthreads();
    int cur = 0;
#pragma unroll 1
    for (int s = 1; s < 32; s++) {
        float m = -1e30f;
#pragma unroll
        for (int k = 0; k < NTAG; k++) m = fmaxf(m, T[n][k] + P[cur][k][p]);
        float sm = 0.f;
#pragma unroll
        for (int k = 0; k < NTAG; k++) sm += __expf(T[n][k] + P[cur][k][p] - m);
        P[cur ^ 1][n][p] = em[s][n] + m + logf(sm);
        __syncthreads();
        cur ^= 1;
    }
    g_P[blockIdx.x][n][p] = P[cur][n][p];
}

// ---------------- kernel E: final combine + gold score ----------------
__global__ void __launch_bounds__(256) crf_final_kernel(const int* __restrict__ tags,
                                                        const float* __restrict__ trans,
                                                        float* __restrict__ out) {
    __shared__ float red[256];
    __shared__ float v[NTAG], nv[NTAG];
    int tid = threadIdx.x;
    // gold path score partials
    float gs = 0.f;
    for (int t = tid; t < SEQT; t += 256) {
        int tg = tags[t];
        int pv = (t == 0) ? STARTT : tags[t - 1];
        gs += trans[tg * NTAG + pv] + g_feats[t][tg];
    }
    red[tid] = gs;
    __syncthreads();
    for (int off = 128; off > 0; off >>= 1) {
        if (tid < off) red[tid] += red[tid + off];
        __syncthreads();
    }
    if (tid < NTAG) v[tid] = (tid == STARTT) ? 0.f : NEGV;
    __syncthreads();
#pragma unroll 1
    for (int cidx = 0; cidx < SEQT / 32; cidx++) {
        if (tid < NTAG) {
            float m = -1e30f;
#pragma unroll
            for (int p = 0; p < NTAG; p++) m = fmaxf(m, g_P[cidx][tid][p] + v[p]);
            float s = 0.f;
#pragma unroll
            for (int p = 0; p < NTAG; p++) s += __expf(g_P[cidx][tid][p] + v[p] - m);
            nv[tid] = m + logf(s);
        }
        __syncthreads();
        if (tid < NTAG) v[tid] = nv[tid];
        __syncthreads();
    }
    if (tid == 0) {
        float m = -1e30f;
#pragma unroll
        for (int n = 0; n < NTAG; n++) m = fmaxf(m, v[n] + trans[STOPT * NTAG + n]);
        float s = 0.f;
#pragma unroll
        for (int n = 0; n < NTAG; n++) s += __expf(v[n] + trans[STOPT * NTAG + n] - m);
        float fwd = m + logf(s);
        float gold = red[0] + trans[STOPT * NTAG + tags[SEQT - 1]];
        out[0] = fwd - gold;
    }
}

// ---------------- launch ----------------
extern "C" void kernel_launch(void* const* d_in, const int* in_sizes, int n_in,
                              void* d_out, int out_size) {
    const int* sent = (const int*)d_in[0];
    const int* tags = (const int*)d_in[1];
    const float* embed = (const float*)d_in[2];
    const float* Wih_f = (const float*)d_in[3];
    const float* Whh_f = (const float*)d_in[4];
    const float* bih_f = (const float*)d_in[5];
    const float* bhh_f = (const float*)d_in[6];
    const float* Wih_b = (const float*)d_in[7];
    const float* Whh_b = (const float*)d_in[8];
    const float* bih_b = (const float*)d_in[9];
    const float* bhh_b = (const float*)d_in[10];
    const float* W_out = (const float*)d_in[11];
    const float* b_out = (const float*)d_in[12];
    const float* h0 = (const float*)d_in[13];
    const float* c0 = (const float*)d_in[14];
    const float* trans = (const float*)d_in[15];
    float* out = (float*)d_out;

    proj_kernel<<<512, 256>>>(sent, embed, Wih_f, bih_f, bhh_f, Wih_b, bih_b, bhh_b);
    lstm_kernel<<<16, 512>>>(Whh_f, Whh_b, h0, c0);
    feats_kernel<<<SEQT, 128>>>(W_out, b_out);
    crf_chunk_kernel<<<SEQT / 32, 144>>>(trans);
    crf_final_kernel<<<1, 256>>>(tags, trans, out);
}